// round 1
// baseline (speedup 1.0000x reference)
#include <cuda_runtime.h>

#define NN 8192
#define DD 128
#define PP 4
#define KK 512           // P*D concatenated feature dim
#define EPS 0.3f

// Scratch (allocation is banned -> __device__ globals)
__device__ float d_Y[(size_t)NN * KK];          // 16 MB: folded/normalized features
__device__ float d_og[(size_t)NN * NN];         // 256 MB: dense original adjacency

// ---------------------------------------------------------------------------
// Zero the dense adjacency
// ---------------------------------------------------------------------------
__global__ void zero_og_kernel() {
    size_t n4 = (size_t)NN * NN / 4;
    float4* p = (float4*)d_og;
    size_t stride = (size_t)gridDim.x * blockDim.x;
    for (size_t i = (size_t)blockIdx.x * blockDim.x + threadIdx.x; i < n4; i += stride)
        p[i] = make_float4(0.f, 0.f, 0.f, 0.f);
}

// ---------------------------------------------------------------------------
// Scatter edges (duplicates add)
// ---------------------------------------------------------------------------
__global__ void scatter_kernel(const int* __restrict__ oi,
                               const float* __restrict__ ow, int E) {
    int e = blockIdx.x * blockDim.x + threadIdx.x;
    if (e < E) {
        int src = oi[e];
        int dst = oi[E + e];
        atomicAdd(&d_og[(size_t)src * NN + dst], ow[e]);
    }
}

// ---------------------------------------------------------------------------
// Build Y[i, p*D+d] = 0.5 * (x[i,d]*w[p,d]) / max(||x_i * w_p||, 1e-12)
// (0.5 = 1/sqrt(P), exact power of 2, so Y Y^T == mean_p cosine sims)
// ---------------------------------------------------------------------------
__global__ void buildY_kernel(const float* __restrict__ x,
                              const float* __restrict__ wp) {
    int i = blockIdx.x;
    int d = threadIdx.x;     // 128 threads
    float xv = x[i * DD + d];
    __shared__ float sred[4];
#pragma unroll
    for (int p = 0; p < PP; p++) {
        float v = xv * wp[p * DD + d];
        float s = v * v;
#pragma unroll
        for (int o = 16; o > 0; o >>= 1)
            s += __shfl_xor_sync(0xffffffffu, s, o);
        if ((d & 31) == 0) sred[d >> 5] = s;
        __syncthreads();
        float tot = sred[0] + sred[1] + sred[2] + sred[3];
        float inv = 0.5f / fmaxf(sqrtf(tot), 1e-12f);
        d_Y[(size_t)i * KK + p * DD + d] = v * inv;
        __syncthreads();
    }
}

// ---------------------------------------------------------------------------
// Fused SYRK + epilogue: sim = Y Y^T (upper-triangular block tiles only),
// out[i,j] = (s>eps ? s : 0) + (s*og[i,j]>eps ? og[i,j] : 0), mirrored.
// ---------------------------------------------------------------------------
#define BM 128
#define BN 128
#define BK 16

__global__ __launch_bounds__(256, 2) void gemm_epi_kernel(float* __restrict__ out) {
    int bi = blockIdx.y;
    int bj = blockIdx.x;
    if (bj < bi) return;   // symmetric: only upper-triangular tiles do work

    __shared__ float As[BK][BM + 4];
    __shared__ float Bs[BK][BN + 4];

    int tid = threadIdx.x;
    int tx = tid & 15;       // 0..15 -> col group
    int ty = tid >> 4;       // 0..15 -> row group

    float acc[8][8];
#pragma unroll
    for (int u = 0; u < 8; u++)
#pragma unroll
        for (int v = 0; v < 8; v++) acc[u][v] = 0.f;

    const float* Abase = d_Y + (size_t)bi * BM * KK;
    const float* Bbase = d_Y + (size_t)bj * BN * KK;

    for (int k0 = 0; k0 < KK; k0 += BK) {
        // Load 128x16 A and B tiles, store transposed: 512 float4 each, 2/thread
#pragma unroll
        for (int l = 0; l < 2; l++) {
            int idx = tid + l * 256;      // 0..511
            int r   = idx >> 2;           // row 0..127
            int c4  = idx & 3;            // which float4 in the 16-wide k slab
            float4 va = *(const float4*)(Abase + (size_t)r * KK + k0 + c4 * 4);
            As[c4 * 4 + 0][r] = va.x;
            As[c4 * 4 + 1][r] = va.y;
            As[c4 * 4 + 2][r] = va.z;
            As[c4 * 4 + 3][r] = va.w;
            float4 vb = *(const float4*)(Bbase + (size_t)r * KK + k0 + c4 * 4);
            Bs[c4 * 4 + 0][r] = vb.x;
            Bs[c4 * 4 + 1][r] = vb.y;
            Bs[c4 * 4 + 2][r] = vb.z;
            Bs[c4 * 4 + 3][r] = vb.w;
        }
        __syncthreads();

#pragma unroll
        for (int kk = 0; kk < BK; kk++) {
            float a[8], b[8];
#pragma unroll
            for (int u = 0; u < 8; u++) a[u] = As[kk][ty * 8 + u];
#pragma unroll
            for (int v = 0; v < 8; v++) b[v] = Bs[kk][tx * 8 + v];
#pragma unroll
            for (int u = 0; u < 8; u++)
#pragma unroll
                for (int v = 0; v < 8; v++) acc[u][v] = fmaf(a[u], b[v], acc[u][v]);
        }
        __syncthreads();
    }

    // Fused epilogue with mirror writes
#pragma unroll
    for (int u = 0; u < 8; u++) {
        int gi = bi * BM + ty * 8 + u;
#pragma unroll
        for (int v = 0; v < 8; v++) {
            int gj = bj * BN + tx * 8 + v;
            float s  = acc[u][v];
            float sg = (s > EPS) ? s : 0.f;
            float og = d_og[(size_t)gi * NN + gj];
            out[(size_t)gi * NN + gj] = ((s * og > EPS) ? og : 0.f) + sg;
            if (bi != bj) {
                float og2 = d_og[(size_t)gj * NN + gi];
                out[(size_t)gj * NN + gi] = ((s * og2 > EPS) ? og2 : 0.f) + sg;
            }
        }
    }
}

// ---------------------------------------------------------------------------
extern "C" void kernel_launch(void* const* d_in, const int* in_sizes, int n_in,
                              void* d_out, int out_size) {
    const float* x  = (const float*)d_in[0];
    const int*   oi = (const int*)d_in[1];
    const float* ow = (const float*)d_in[2];
    const float* wp = (const float*)d_in[3];
    float* out = (float*)d_out;
    int E = in_sizes[2];

    zero_og_kernel<<<2048, 256>>>();
    scatter_kernel<<<(E + 255) / 256, 256>>>(oi, ow, E);
    buildY_kernel<<<NN, DD>>>(x, wp);
    dim3 grid(NN / BN, NN / BM);
    gemm_epi_kernel<<<grid, 256>>>(out);
}

// round 5
// speedup vs baseline: 2.5334x; 2.5334x over previous
#include <cuda_runtime.h>
#include <cuda_fp16.h>
#include <cstdint>

#define NN 8192
#define DD 128
#define PP 4
#define KO 512            // original concat feature dim
#define KE 1536           // split-3 extended K
#define EPS 0.3f
#define EMAX (1 << 19)
#define OUT_DESCALE 0.00390625f   // 2^-8 (exact)

// Scratch (allocation banned -> __device__ globals)
__device__ __half d_A[(size_t)NN * KE];   // 24 MB: [hi*2^4 | hi*2^-2 | lo*2^10]
__device__ __half d_B[(size_t)NN * KE];   // 24 MB: [hi*2^4 | lo*2^10 | hi*2^-2]
__device__ float  d_og[(size_t)NN * NN];  // only edge positions ever touched
__device__ float  d_val[EMAX];

// ---------------------------------------------------------------------------
__device__ __forceinline__ uint32_t smem_u32(const void* p) {
    uint32_t a;
    asm("{ .reg .u64 t; cvta.to.shared.u64 t, %1; cvt.u32.u64 %0, t; }" : "=r"(a) : "l"(p));
    return a;
}
__device__ __forceinline__ void ldsm_x4(uint32_t* r, uint32_t addr) {
    asm volatile("ldmatrix.sync.aligned.m8n8.x4.shared.b16 {%0,%1,%2,%3}, [%4];"
                 : "=r"(r[0]), "=r"(r[1]), "=r"(r[2]), "=r"(r[3]) : "r"(addr));
}
// chained accumulate: c = a*b + c  (tensor-unit add)
__device__ __forceinline__ void mma_acc(float* c, const uint32_t* a,
                                        uint32_t b0, uint32_t b1) {
    asm volatile(
        "mma.sync.aligned.m16n8k16.row.col.f32.f16.f16.f32 "
        "{%0,%1,%2,%3},{%4,%5,%6,%7},{%8,%9},{%0,%1,%2,%3};"
        : "+f"(c[0]), "+f"(c[1]), "+f"(c[2]), "+f"(c[3])
        : "r"(a[0]), "r"(a[1]), "r"(a[2]), "r"(a[3]), "r"(b0), "r"(b1));
}
// fresh-segment form: c = a*b + 0  (starts a new short chain)
__device__ __forceinline__ void mma_set(float* c, const uint32_t* a,
                                        uint32_t b0, uint32_t b1) {
    asm volatile(
        "mma.sync.aligned.m16n8k16.row.col.f32.f16.f16.f32 "
        "{%0,%1,%2,%3},{%4,%5,%6,%7},{%8,%9},{%10,%11,%12,%13};"
        : "=f"(c[0]), "=f"(c[1]), "=f"(c[2]), "=f"(c[3])
        : "r"(a[0]), "r"(a[1]), "r"(a[2]), "r"(a[3]), "r"(b0), "r"(b1),
          "f"(0.f), "f"(0.f), "f"(0.f), "f"(0.f));
}
#define CP_ASYNC16(dst, src) \
    asm volatile("cp.async.cg.shared.global [%0], [%1], 16;" :: "r"(dst), "l"(src))
#define CP_COMMIT() asm volatile("cp.async.commit_group;" ::: "memory")
#define CP_WAIT1()  asm volatile("cp.async.wait_group 1;" ::: "memory")

// ---------------------------------------------------------------------------
// Edge kernels (no dense memset: only edge positions are ever touched)
// ---------------------------------------------------------------------------
__global__ void zero_edges_kernel(const int* __restrict__ oi, int E) {
    int e = blockIdx.x * blockDim.x + threadIdx.x;
    if (e < E) d_og[(size_t)oi[e] * NN + oi[E + e]] = 0.f;
}
__global__ void scatter_kernel(const int* __restrict__ oi,
                               const float* __restrict__ ow, int E) {
    int e = blockIdx.x * blockDim.x + threadIdx.x;
    if (e < E) atomicAdd(&d_og[(size_t)oi[e] * NN + oi[E + e]], ow[e]);
}

// ---------------------------------------------------------------------------
// Build split operands: y = 0.5*(x*w)/||x*w||; hi = fp16(y), lo = y - hi.
// Block scaling keeps every fp16 value in the NORMAL range:
// A = [hi*16 | hi/4 | lo*1024], B = [hi*16 | lo*1024 | hi/4]
// Every block-product has scale 2^8; epilogue de-scales by 2^-8 (exact).
// ---------------------------------------------------------------------------
__global__ void buildY_kernel(const float* __restrict__ x,
                              const float* __restrict__ wp) {
    int i = blockIdx.x;
    int d = threadIdx.x;   // 128 threads
    float xv = x[i * DD + d];
    __shared__ float sred[4];
#pragma unroll
    for (int p = 0; p < PP; p++) {
        float v = xv * wp[p * DD + d];
        float s = v * v;
#pragma unroll
        for (int o = 16; o > 0; o >>= 1) s += __shfl_xor_sync(0xffffffffu, s, o);
        if ((d & 31) == 0) sred[d >> 5] = s;
        __syncthreads();
        float tot = sred[0] + sred[1] + sred[2] + sred[3];
        float inv = 0.5f / fmaxf(sqrtf(tot), 1e-12f);
        float yv = v * inv;
        float hf = __half2float(__float2half_rn(yv));
        float lo = yv - hf;
        __half h16  = __float2half_rn(hf * 16.0f);      // exact scale
        __half hq   = __float2half_rn(hf * 0.25f);      // exact scale
        __half l1k  = __float2half_rn(lo * 1024.0f);
        size_t base = (size_t)i * KE;
        int k = p * DD + d;
        d_A[base + k]          = h16;
        d_A[base + KO + k]     = hq;
        d_A[base + 2 * KO + k] = l1k;
        d_B[base + k]          = h16;
        d_B[base + KO + k]     = l1k;
        d_B[base + 2 * KO + k] = hq;
        __syncthreads();
    }
}

// ---------------------------------------------------------------------------
// HMMA fp16 SYRK (K=1536), segmented accumulation (short tensor-unit chains,
// RN drains into fp32 register sums), thresholded epilogue, upper-tri tiles
// ---------------------------------------------------------------------------
#define STAGES 3
#define KSTEP 64
#define NSTEPS (KE / KSTEP)        // 24
#define SEG 2                      // k-steps per accumulation segment
#define TILE_BYTES 16384           // 128 rows x 128B
#define STAGE_BYTES (2 * TILE_BYTES)

__global__ __launch_bounds__(256, 1) void gemm_hmma_kernel(float* __restrict__ out) {
    int bi = blockIdx.y, bj = blockIdx.x;
    if (bj < bi) return;           // symmetric: upper-triangular tiles only

    extern __shared__ char dsm[];
    uint32_t smem = smem_u32(dsm);
    int tid = threadIdx.x, wid = tid >> 5, lane = tid & 31;
    int wr = wid >> 1, wc = wid & 1;   // warp tile: rows wr*32, cols wc*64

    const __half* Ag = d_A + (size_t)bi * 128 * KE;
    const __half* Bg = d_B + (size_t)bj * 128 * KE;

    // prefetch into stage ks%3 (always commits -> stable group count)
    auto prefetch = [&](int ks) {
        if (ks < NSTEPS) {
            uint32_t sa = smem + (ks % STAGES) * STAGE_BYTES;
            uint32_t sb = sa + TILE_BYTES;
            const __half* ga = Ag + ks * KSTEP;
            const __half* gb = Bg + ks * KSTEP;
#pragma unroll
            for (int l = 0; l < 4; l++) {
                int id = l * 256 + tid;        // 1024 16B-chunks per matrix
                int r = id >> 3, c = id & 7;
                uint32_t off = r * 128 + ((c ^ (r & 7)) << 4);  // SW128 swizzle
                CP_ASYNC16(sa + off, ga + (size_t)r * KE + c * 8);
                CP_ASYNC16(sb + off, gb + (size_t)r * KE + c * 8);
            }
        }
        CP_COMMIT();
    };

    float acc[2][8][4];    // tensor-unit working accumulator (short chains)
    float csum[2][8][4];   // RN-drained running sum
#pragma unroll
    for (int mt = 0; mt < 2; mt++)
#pragma unroll
        for (int nt = 0; nt < 8; nt++)
#pragma unroll
            for (int q = 0; q < 4; q++) csum[mt][nt][q] = 0.f;

    // per-lane ldmatrix address pieces
    int aRow = lane & 15;            // + wr*32 + mt*16
    int aHalf = lane >> 4;           // +0/+1 16B chunk
    int bRow = (lane & 7) + ((lane >> 4) << 3);
    int bHalf = (lane >> 3) & 1;

    prefetch(0);
    prefetch(1);

    for (int ks = 0; ks < NSTEPS; ks++) {
        CP_WAIT1();
        __syncthreads();
        prefetch(ks + 2);

        uint32_t sa = smem + (ks % STAGES) * STAGE_BYTES;
        uint32_t sb = sa + TILE_BYTES;
        bool segStart = (ks % SEG) == 0;
#pragma unroll
        for (int k16 = 0; k16 < 4; k16++) {
            uint32_t a[2][4];
#pragma unroll
            for (int mt = 0; mt < 2; mt++) {
                int r = wr * 32 + mt * 16 + aRow;
                int c = 2 * k16 + aHalf;
                ldsm_x4(a[mt], sa + r * 128 + ((c ^ (r & 7)) << 4));
            }
            uint32_t b[4][4];
#pragma unroll
            for (int np = 0; np < 4; np++) {
                int r = wc * 64 + np * 16 + bRow;
                int c = 2 * k16 + bHalf;
                ldsm_x4(b[np], sb + r * 128 + ((c ^ (r & 7)) << 4));
            }
            if (segStart && k16 == 0) {
#pragma unroll
                for (int mt = 0; mt < 2; mt++)
#pragma unroll
                    for (int np = 0; np < 4; np++) {
                        mma_set(acc[mt][2 * np],     a[mt], b[np][0], b[np][1]);
                        mma_set(acc[mt][2 * np + 1], a[mt], b[np][2], b[np][3]);
                    }
            } else {
#pragma unroll
                for (int mt = 0; mt < 2; mt++)
#pragma unroll
                    for (int np = 0; np < 4; np++) {
                        mma_acc(acc[mt][2 * np],     a[mt], b[np][0], b[np][1]);
                        mma_acc(acc[mt][2 * np + 1], a[mt], b[np][2], b[np][3]);
                    }
            }
        }
        if ((ks % SEG) == SEG - 1) {   // drain segment with RN FADDs
#pragma unroll
            for (int mt = 0; mt < 2; mt++)
#pragma unroll
                for (int nt = 0; nt < 8; nt++)
#pragma unroll
                    for (int q = 0; q < 4; q++)
                        csum[mt][nt][q] += acc[mt][nt][q];
        }
    }

    // Epilogue: de-scale (2^-8), threshold, write row block; mirror lower tri
    int g = lane >> 2, tg = lane & 3;
#pragma unroll
    for (int mt = 0; mt < 2; mt++) {
#pragma unroll
        for (int h = 0; h < 2; h++) {
            int gi = bi * 128 + wr * 32 + mt * 16 + h * 8 + g;
            float* rowp = out + (size_t)gi * NN + bj * 128 + wc * 64 + tg * 2;
#pragma unroll
            for (int nt = 0; nt < 8; nt++) {
                float s0 = csum[mt][nt][2 * h] * OUT_DESCALE;
                float s1 = csum[mt][nt][2 * h + 1] * OUT_DESCALE;
                s0 = (s0 > EPS) ? s0 : 0.f;
                s1 = (s1 > EPS) ? s1 : 0.f;
                *(float2*)(rowp + nt * 8) = make_float2(s0, s1);
                if (bi != bj) {
                    int gj = bj * 128 + wc * 64 + nt * 8 + tg * 2;
                    out[(size_t)gj * NN + gi] = s0;
                    out[(size_t)(gj + 1) * NN + gi] = s1;
                }
            }
        }
    }
}

// ---------------------------------------------------------------------------
// Per-edge purification fixup (race-free, duplicate-idempotent)
// ---------------------------------------------------------------------------
__global__ void edge_fix_a(const int* __restrict__ oi,
                           const float* __restrict__ out, int E) {
    int e = blockIdx.x * blockDim.x + threadIdx.x;
    if (e >= E) return;
    int i = oi[e], j = oi[E + e];
    float og = d_og[(size_t)i * NN + j];
    float so = out[(size_t)i * NN + j];   // sim_g = sim if sim>eps else 0
    float s = so;
    if (so == 0.f) {
        // here sim <= eps, so sim*og > eps requires og > 1 (duplicate edges only)
        if (og > 1.0f) {
            const __half* ai = d_A + (size_t)i * KE;
            const __half* bj = d_B + (size_t)j * KE;
            float acc = 0.f;
#pragma unroll 4
            for (int k = 0; k < KO; k++) {
                float yi = __half2float(ai[k]) * 0.0625f +
                           __half2float(ai[2 * KO + k]) * 0.0009765625f;
                float yj = __half2float(bj[k]) * 0.0625f +
                           __half2float(bj[KO + k]) * 0.0009765625f;
                acc = fmaf(yi, yj, acc);
            }
            s = acc;
        } else {
            s = 0.f;
        }
    }
    d_val[e] = so + ((s * og > EPS) ? og : 0.f);
}
__global__ void edge_fix_b(const int* __restrict__ oi, float* __restrict__ out, int E) {
    int e = blockIdx.x * blockDim.x + threadIdx.x;
    if (e >= E) return;
    out[(size_t)oi[e] * NN + oi[E + e]] = d_val[e];
}

// ---------------------------------------------------------------------------
extern "C" void kernel_launch(void* const* d_in, const int* in_sizes, int n_in,
                              void* d_out, int out_size) {
    const float* x  = (const float*)d_in[0];
    const int*   oi = (const int*)d_in[1];
    const float* ow = (const float*)d_in[2];
    const float* wp = (const float*)d_in[3];
    float* out = (float*)d_out;
    int E = in_sizes[2];

    cudaFuncSetAttribute(gemm_hmma_kernel,
                         cudaFuncAttributeMaxDynamicSharedMemorySize,
                         STAGES * STAGE_BYTES);

    zero_edges_kernel<<<(E + 255) / 256, 256>>>(oi, E);
    scatter_kernel<<<(E + 255) / 256, 256>>>(oi, ow, E);
    buildY_kernel<<<NN, DD>>>(x, wp);
    dim3 grid(NN / 128, NN / 128);
    gemm_hmma_kernel<<<grid, 256, STAGES * STAGE_BYTES>>>(out);
    edge_fix_a<<<(E + 255) / 256, 256>>>(oi, out, E);
    edge_fix_b<<<(E + 255) / 256, 256>>>(oi, out, E);
}